// round 15
// baseline (speedup 1.0000x reference)
#include <cuda_runtime.h>
#include <math.h>

// x (2,16,256,256) f32, conv_w (32,16,4,4), conv_b (32) -> out (2,32,256,256) f32.
// Ring of 40 offsets (radius 5), stable-select 16 smallest sigmoid-sims,
// rank-indexed 32x(16*16) mat-vec per pixel.
// R14 structure (float4 halo, LDS.128 gathers, __expf sigmoid, FFMA dot) with:
//  - wsum prepass + NEGATED weights: out = bias + sum_c wsum[c,o]*xc[c]
//      + sum_{r,c} (-w)[r,c,o]*xr   -> no FSUB in hot loop, xc regs freed
//  - next-rank sel prefetch (hides sel->gather serial latency)

#define B_      2
#define CCH     16
#define NC4     (CCH/4)        // 4 float4 channel-groups
#define HH      256
#define WWIDTH  256
#define HW      (HH*WWIDTH)
#define OUTC    32
#define NOFF    40
#define NSEL    16

#define TW 32
#define TH 8
#define NTHR (TW*TH)           // 256
#define SW 42                  // TW + 2*5
#define SH 18                  // TH + 2*5
#define CPLANE (SW*SH)         // 756
#define XS_FLOATS (CPLANE*CCH)        // 12096
#define WS_FLOATS (NSEL*CCH*OUTC)     // 8192
#define WSUM_FLOATS (CCH*OUTC)        // 512
#define CB_FLOATS 32
// smem: xs + ws + wsum + cbs + selp(u16 [rank][tid] = 8192B)
#define SMEM_BYTES ((XS_FLOATS + WS_FLOATS + WSUM_FLOATS + CB_FLOATS)*4 + NSEL*NTHR*2)

// Ring offsets, order matching _prf_offsets:
//  j 0..10 : dx=-5,   dy=j-5
//  j 11..19: dx=j-15, dy=+5
//  j 20..30: dx=+5,   dy=j-25
//  j 31..39: dx=j-35, dy=-5
__host__ __device__ constexpr int dxOf(int j){ return j<11 ? -5 : (j<20 ? j-15 : (j<31 ? 5 : j-35)); }
__host__ __device__ constexpr int dyOf(int j){ return j<11 ? j-5 : (j<20 ? 5 : (j<31 ? j-25 : -5)); }
__host__ __device__ constexpr int offOf(int j){ return dxOf(j)*SW + dyOf(j); }

typedef unsigned long long u64;

__device__ __forceinline__ u64 pack2(float a, float b){
    u64 r;
    asm("mov.b64 %0, {%1,%2};" : "=l"(r) : "f"(a), "f"(b));
    return r;
}
__device__ __forceinline__ void fma2(u64 &acc, u64 a, u64 b){
    asm("fma.rn.f32x2 %0, %1, %2, %0;" : "+l"(acc) : "l"(a), "l"(b));
}
__device__ __forceinline__ float2 unpack2(u64 v){
    float2 f;
    asm("mov.b64 {%0,%1}, %2;" : "=f"(f.x), "=f"(f.y) : "l"(v));
    return f;
}

__global__ __launch_bounds__(NTHR, 2)
void pkc2d_kernel(const float* __restrict__ x,
                  const float* __restrict__ cw,
                  const float* __restrict__ cb,
                  float* __restrict__ out)
{
    extern __shared__ float sm[];
    float4*         xs4  = reinterpret_cast<float4*>(sm);       // [c4][plane]
    float*          ws   = sm + XS_FLOATS;                      // [r][c][o] NEGATED
    float*          wsum = ws + WS_FLOATS;                      // [c][o] sum_r w
    float*          cbs  = wsum + WSUM_FLOATS;                  // [32]
    unsigned short* selp = (unsigned short*)(cbs + CB_FLOATS);  // [rank][tid]

    const int tx = threadIdx.x, ty = threadIdx.y;
    const int tid = ty*TW + tx;
    const int gx0 = blockIdx.x*TW, gy0 = blockIdx.y*TH;
    const int bz  = blockIdx.z;

    const float* xb = x + (size_t)bz * CCH * HW;

    // ---- cooperative halo load: 4-channel float4 groups ----
    for (int i = tid; i < CPLANE*NC4; i += NTHR) {
        int c4   = i / CPLANE;
        int cell = i - c4*CPLANE;
        int sy   = cell / SW;
        int sx   = cell - sy*SW;
        int gy   = gy0 + sy - 5;
        int gxp  = gx0 + sx - 5;
        float4 v = make_float4(0.f, 0.f, 0.f, 0.f);
        if ((unsigned)gy < (unsigned)HH && (unsigned)gxp < (unsigned)WWIDTH) {
            const float* p = xb + (4*c4)*HW + gy*WWIDTH + gxp;
            v.x = p[0];
            v.y = p[HW];
            v.z = p[2*HW];
            v.w = p[3*HW];
        }
        xs4[i] = v;
    }
    // ws[((r*16)+c)*32 + o] = -cw[o*256 + c*16 + r]   (negated)
    for (int i = tid; i < WS_FLOATS; i += NTHR) {
        int o  = i & 31;
        int rc = i >> 5;
        int r  = rc >> 4;
        int c  = rc & 15;
        ws[i] = -cw[o*256 + c*16 + r];
    }
    // wsum[c*32+o] = sum_r cw[o*256+c*16+r]
    for (int j = tid; j < WSUM_FLOATS; j += NTHR) {
        int o = j & 31;
        int c = j >> 5;
        const float4* p = reinterpret_cast<const float4*>(cw + o*256 + c*16);
        float4 a = p[0], b = p[1], cc = p[2], d = p[3];
        wsum[j] = ((a.x+a.y)+(a.z+a.w)) + ((b.x+b.y)+(b.z+b.w))
                + ((cc.x+cc.y)+(cc.z+cc.w)) + ((d.x+d.y)+(d.z+d.w));
    }
    if (tid < 32) cbs[tid] = cb[tid];
    __syncthreads();

    // ================= Phase 1: selection (bit-exact vs R14) =================
    {
        const int base = (ty+5)*SW + (tx+5);

        float4 xc[NC4];
        #pragma unroll
        for (int c4 = 0; c4 < NC4; ++c4) xc[c4] = xs4[c4*CPLANE + base];

        // FFMA-contracted sequential channel-order dot, then sigmoid
        // (REQUIRED per R5; ulp-robustness verified R13/R14).
        float sims[NOFF];
        #pragma unroll
        for (int j = 0; j < NOFF; ++j) {
            const int off = offOf(j);
            float s = 0.f;
            #pragma unroll
            for (int c4 = 0; c4 < NC4; ++c4) {
                const float4 v = xs4[c4*CPLANE + base + off];
                s = __fmaf_rn(v.x, xc[c4].x, s);
                s = __fmaf_rn(v.y, xc[c4].y, s);
                s = __fmaf_rn(v.z, xc[c4].z, s);
                s = __fmaf_rn(v.w, xc[c4].w, s);
            }
            sims[j] = __frcp_rn(1.0f + __expf(s * -0.0625f));
        }

        // Stable argsort rank, one compare per unordered pair (proven R4/R6).
        int rk[NOFF];
        #pragma unroll
        for (int i = 0; i < NOFF; ++i) rk[i] = NOFF - 1 - i;
        #pragma unroll
        for (int i = 0; i < NOFF; ++i) {
            #pragma unroll
            for (int j = i+1; j < NOFF; ++j) {
                if (sims[i] <= sims[j]) { rk[j] += 1; rk[i] -= 1; }
            }
        }
        #pragma unroll
        for (int j = 0; j < NOFF; ++j) {
            if (rk[j] < NSEL)
                selp[rk[j]*NTHR + tid] = (unsigned short)(offOf(j) + 512);
        }
    }
    __syncthreads();

    // ================= Phase 2: pixel-pair / half-OUTC mat-vec =================
    const int pp = tid & 127;
    const int ph = tid >> 7;
    const int px = pp & 31;
    const int py = pp >> 5;

    const int b0 = (py+5)*SW + (px+5);
    const int b1 = b0 + 4*SW;

    u64 accA[8], accB[8];
    #pragma unroll
    for (int q = 0; q < 8; ++q) {
        u64 seed = pack2(cbs[ph*16 + 2*q], cbs[ph*16 + 2*q + 1]);
        accA[q] = seed;
        accB[q] = seed;
    }

    // ---- prepass: acc += wsum[c][o]*xc[c]; xc dies afterwards ----
    {
        const ulonglong2* wq = reinterpret_cast<const ulonglong2*>(wsum) + (ph << 2);
        #pragma unroll
        for (int c4 = 0; c4 < NC4; ++c4) {
            const float4 v0 = xs4[c4*CPLANE + b0];
            const float4 v1 = xs4[c4*CPLANE + b1];
            u64 dA, dB;
            #define CH_BLOCK(comp, choff)                                        \
            {                                                                    \
                dA = pack2(v0.comp, v0.comp);                                    \
                dB = pack2(v1.comp, v1.comp);                                    \
                const ulonglong2* wc_ = wq + (4*c4 + (choff))*8;                 \
                ulonglong2 w0 = wc_[0], w1 = wc_[1], w2 = wc_[2], w3 = wc_[3];   \
                fma2(accA[0], w0.x, dA); fma2(accB[0], w0.x, dB);                \
                fma2(accA[1], w0.y, dA); fma2(accB[1], w0.y, dB);                \
                fma2(accA[2], w1.x, dA); fma2(accB[2], w1.x, dB);                \
                fma2(accA[3], w1.y, dA); fma2(accB[3], w1.y, dB);                \
                fma2(accA[4], w2.x, dA); fma2(accB[4], w2.x, dB);                \
                fma2(accA[5], w2.y, dA); fma2(accB[5], w2.y, dB);                \
                fma2(accA[6], w3.x, dA); fma2(accB[6], w3.x, dB);                \
                fma2(accA[7], w3.y, dA); fma2(accB[7], w3.y, dB);                \
            }
            CH_BLOCK(x, 0)
            CH_BLOCK(y, 1)
            CH_BLOCK(z, 2)
            CH_BLOCK(w, 3)
        }
    }

    // ---- main loop: acc += (-w)[r][c][o]*xr ; sel prefetched one rank ahead ----
    int a0 = b0 + (int)selp[pp]       - 512;
    int a1 = b1 + (int)selp[pp + 128] - 512;
    #pragma unroll 1
    for (int r = 0; r < NSEL; ++r) {
        const int ca0 = a0, ca1 = a1;
        if (r + 1 < NSEL) {
            a0 = b0 + (int)selp[(r+1)*NTHR + pp]       - 512;
            a1 = b1 + (int)selp[(r+1)*NTHR + pp + 128] - 512;
        }
        const ulonglong2* wq =
            reinterpret_cast<const ulonglong2*>(ws + (r << 9) + (ph << 4));
        #pragma unroll
        for (int c4 = 0; c4 < NC4; ++c4) {
            const float4 v0 = xs4[c4*CPLANE + ca0];
            const float4 v1 = xs4[c4*CPLANE + ca1];
            u64 dA, dB;
            CH_BLOCK(x, 0)
            CH_BLOCK(y, 1)
            CH_BLOCK(z, 2)
            CH_BLOCK(w, 3)
        }
    }
    #undef CH_BLOCK

    // ---- store: 16 o-channels x 2 pixels ----
    const int gx = gx0 + px;
    const int gy_a = gy0 + py;
    const int gy_b = gy_a + 4;
    float* ob = out + (size_t)bz*OUTC*HW + (size_t)(ph*16)*HW + gx;
    #pragma unroll
    for (int q = 0; q < 8; ++q) {
        float2 va = unpack2(accA[q]);
        float2 vb = unpack2(accB[q]);
        ob[(2*q  )*HW + gy_a*WWIDTH] = va.x;
        ob[(2*q+1)*HW + gy_a*WWIDTH] = va.y;
        ob[(2*q  )*HW + gy_b*WWIDTH] = vb.x;
        ob[(2*q+1)*HW + gy_b*WWIDTH] = vb.y;
    }
}

extern "C" void kernel_launch(void* const* d_in, const int* in_sizes, int n_in,
                              void* d_out, int out_size)
{
    const float* x  = (const float*)d_in[0];
    const float* cw = (const float*)d_in[1];
    const float* cb = (const float*)d_in[2];
    float* out = (float*)d_out;

    cudaFuncSetAttribute(pkc2d_kernel,
                         cudaFuncAttributeMaxDynamicSharedMemorySize, SMEM_BYTES);

    dim3 block(TW, TH, 1);
    dim3 grid(WWIDTH/TW, HH/TH, B_);
    pkc2d_kernel<<<grid, block, SMEM_BYTES>>>(x, cw, cb, out);
}

// round 16
// speedup vs baseline: 1.0947x; 1.0947x over previous
#include <cuda_runtime.h>
#include <math.h>

// x (2,16,256,256) f32, conv_w (32,16,4,4), conv_b (32) -> out (2,32,256,256) f32.
// Ring of 40 offsets (radius 5), stable-select 16 smallest sigmoid-sims,
// rank-indexed 32x(16*16) mat-vec per pixel.
// R14 structure (float4 halo, LDS.128 gathers, __expf sigmoid, FFMA dot,
// d=xc-xr form — proven best) with MUFU.RCP (rcp.approx) sigmoid reciprocal.

#define B_      2
#define CCH     16
#define NC4     (CCH/4)        // 4 float4 channel-groups
#define HH      256
#define WWIDTH  256
#define HW      (HH*WWIDTH)
#define OUTC    32
#define NOFF    40
#define NSEL    16

#define TW 32
#define TH 8
#define NTHR (TW*TH)           // 256
#define SW 42                  // TW + 2*5
#define SH 18                  // TH + 2*5
#define CPLANE (SW*SH)         // 756
#define XS_FLOATS (CPLANE*CCH)        // 12096
#define WS_FLOATS (NSEL*CCH*OUTC)     // 8192
#define CB_FLOATS 32
// smem: xs + ws + cbs + selp(u16 [rank][tid] = 8192B)
#define SMEM_BYTES ((XS_FLOATS + WS_FLOATS + CB_FLOATS)*4 + NSEL*NTHR*2)

// Ring offsets, order matching _prf_offsets:
//  j 0..10 : dx=-5,   dy=j-5
//  j 11..19: dx=j-15, dy=+5
//  j 20..30: dx=+5,   dy=j-25
//  j 31..39: dx=j-35, dy=-5
__host__ __device__ constexpr int dxOf(int j){ return j<11 ? -5 : (j<20 ? j-15 : (j<31 ? 5 : j-35)); }
__host__ __device__ constexpr int dyOf(int j){ return j<11 ? j-5 : (j<20 ? 5 : (j<31 ? j-25 : -5)); }
__host__ __device__ constexpr int offOf(int j){ return dxOf(j)*SW + dyOf(j); }

typedef unsigned long long u64;

__device__ __forceinline__ u64 pack2(float a, float b){
    u64 r;
    asm("mov.b64 %0, {%1,%2};" : "=l"(r) : "f"(a), "f"(b));
    return r;
}
__device__ __forceinline__ void fma2(u64 &acc, u64 a, u64 b){
    asm("fma.rn.f32x2 %0, %1, %2, %0;" : "+l"(acc) : "l"(a), "l"(b));
}
__device__ __forceinline__ float2 unpack2(u64 v){
    float2 f;
    asm("mov.b64 {%0,%1}, %2;" : "=f"(f.x), "=f"(f.y) : "l"(v));
    return f;
}
__device__ __forceinline__ float rcp_approx(float v){
    float r;
    asm("rcp.approx.f32 %0, %1;" : "=f"(r) : "f"(v));
    return r;
}

__global__ __launch_bounds__(NTHR, 2)
void pkc2d_kernel(const float* __restrict__ x,
                  const float* __restrict__ cw,
                  const float* __restrict__ cb,
                  float* __restrict__ out)
{
    extern __shared__ float sm[];
    float4*         xs4  = reinterpret_cast<float4*>(sm);       // [c4][plane]
    float*          ws   = sm + XS_FLOATS;                      // [r][c][o]
    float*          cbs  = ws + WS_FLOATS;                      // [32]
    unsigned short* selp = (unsigned short*)(cbs + CB_FLOATS);  // [rank][tid]

    const int tx = threadIdx.x, ty = threadIdx.y;
    const int tid = ty*TW + tx;
    const int gx0 = blockIdx.x*TW, gy0 = blockIdx.y*TH;
    const int bz  = blockIdx.z;

    const float* xb = x + (size_t)bz * CCH * HW;

    // ---- cooperative halo load: 4-channel float4 groups ----
    for (int i = tid; i < CPLANE*NC4; i += NTHR) {
        int c4   = i / CPLANE;
        int cell = i - c4*CPLANE;
        int sy   = cell / SW;
        int sx   = cell - sy*SW;
        int gy   = gy0 + sy - 5;
        int gxp  = gx0 + sx - 5;
        float4 v = make_float4(0.f, 0.f, 0.f, 0.f);
        if ((unsigned)gy < (unsigned)HH && (unsigned)gxp < (unsigned)WWIDTH) {
            const float* p = xb + (4*c4)*HW + gy*WWIDTH + gxp;
            v.x = p[0];
            v.y = p[HW];
            v.z = p[2*HW];
            v.w = p[3*HW];
        }
        xs4[i] = v;
    }
    // ws[((r*16)+c)*32 + o] = cw[o*256 + c*16 + r]
    for (int i = tid; i < WS_FLOATS; i += NTHR) {
        int o  = i & 31;
        int rc = i >> 5;
        int r  = rc >> 4;
        int c  = rc & 15;
        ws[i] = cw[o*256 + c*16 + r];
    }
    if (tid < 32) cbs[tid] = cb[tid];
    __syncthreads();

    // ================= Phase 1: selection =================
    {
        const int base = (ty+5)*SW + (tx+5);

        float4 xc[NC4];
        #pragma unroll
        for (int c4 = 0; c4 < NC4; ++c4) xc[c4] = xs4[c4*CPLANE + base];

        // sims: FFMA-contracted sequential channel-order dot, then sigmoid.
        // Sigmoid REQUIRED (R5: its rounding creates index-broken ties).
        // ulp-scale perturbations proven harmless (R13: __expf ~2ulp,
        // R14: FFMA <=1ulp — zero selections flipped). rcp.approx is the
        // same perturbation class on values in (1,2].
        float sims[NOFF];
        #pragma unroll
        for (int j = 0; j < NOFF; ++j) {
            const int off = offOf(j);
            float s = 0.f;
            #pragma unroll
            for (int c4 = 0; c4 < NC4; ++c4) {
                const float4 v = xs4[c4*CPLANE + base + off];
                s = __fmaf_rn(v.x, xc[c4].x, s);
                s = __fmaf_rn(v.y, xc[c4].y, s);
                s = __fmaf_rn(v.z, xc[c4].z, s);
                s = __fmaf_rn(v.w, xc[c4].w, s);
            }
            sims[j] = rcp_approx(1.0f + __expf(s * -0.0625f));
        }

        // Stable argsort rank, one compare per unordered pair (proven R4/R6).
        int rk[NOFF];
        #pragma unroll
        for (int i = 0; i < NOFF; ++i) rk[i] = NOFF - 1 - i;
        #pragma unroll
        for (int i = 0; i < NOFF; ++i) {
            #pragma unroll
            for (int j = i+1; j < NOFF; ++j) {
                if (sims[i] <= sims[j]) { rk[j] += 1; rk[i] -= 1; }
            }
        }
        #pragma unroll
        for (int j = 0; j < NOFF; ++j) {
            if (rk[j] < NSEL)
                selp[rk[j]*NTHR + tid] = (unsigned short)(offOf(j) + 512);
        }
    }
    __syncthreads();

    // ================= Phase 2: pixel-pair / half-OUTC mat-vec =================
    // thread t: ph = t>>7 -> o in [16*ph, 16*ph+16); pixels p0 = t&127 (rows 0..3)
    // and p1 = p0+128 (rows 4..7) of the 32x8 tile.
    const int pp = tid & 127;
    const int ph = tid >> 7;
    const int px = pp & 31;
    const int py = pp >> 5;

    const int b0 = (py+5)*SW + (px+5);
    const int b1 = b0 + 4*SW;

    float4 xc0[NC4], xc1[NC4];
    #pragma unroll
    for (int c4 = 0; c4 < NC4; ++c4) {
        xc0[c4] = xs4[c4*CPLANE + b0];
        xc1[c4] = xs4[c4*CPLANE + b1];
    }

    u64 accA[8], accB[8];
    #pragma unroll
    for (int q = 0; q < 8; ++q) {
        u64 seed = pack2(cbs[ph*16 + 2*q], cbs[ph*16 + 2*q + 1]);
        accA[q] = seed;
        accB[q] = seed;
    }

    #pragma unroll 1
    for (int r = 0; r < NSEL; ++r) {
        const int a0 = b0 + (int)selp[r*NTHR + pp]       - 512;
        const int a1 = b1 + (int)selp[r*NTHR + pp + 128] - 512;
        const ulonglong2* wq =
            reinterpret_cast<const ulonglong2*>(ws + (r << 9) + (ph << 4));
        #pragma unroll
        for (int c4 = 0; c4 < NC4; ++c4) {
            const float4 v0 = xs4[c4*CPLANE + a0];
            const float4 v1 = xs4[c4*CPLANE + a1];
            u64 dA, dB;
            #define CH_BLOCK(comp, choff)                                        \
            {                                                                    \
                dA = pack2(xc0[c4].comp - v0.comp, xc0[c4].comp - v0.comp);      \
                dB = pack2(xc1[c4].comp - v1.comp, xc1[c4].comp - v1.comp);      \
                const ulonglong2* wc_ = wq + (4*c4 + (choff))*8;                 \
                ulonglong2 w0 = wc_[0], w1 = wc_[1], w2 = wc_[2], w3 = wc_[3];   \
                fma2(accA[0], w0.x, dA); fma2(accB[0], w0.x, dB);                \
                fma2(accA[1], w0.y, dA); fma2(accB[1], w0.y, dB);                \
                fma2(accA[2], w1.x, dA); fma2(accB[2], w1.x, dB);                \
                fma2(accA[3], w1.y, dA); fma2(accB[3], w1.y, dB);                \
                fma2(accA[4], w2.x, dA); fma2(accB[4], w2.x, dB);                \
                fma2(accA[5], w2.y, dA); fma2(accB[5], w2.y, dB);                \
                fma2(accA[6], w3.x, dA); fma2(accB[6], w3.x, dB);                \
                fma2(accA[7], w3.y, dA); fma2(accB[7], w3.y, dB);                \
            }
            CH_BLOCK(x, 0)
            CH_BLOCK(y, 1)
            CH_BLOCK(z, 2)
            CH_BLOCK(w, 3)
            #undef CH_BLOCK
        }
    }

    // ---- store: 16 o-channels x 2 pixels ----
    const int gx = gx0 + px;
    const int gy_a = gy0 + py;
    const int gy_b = gy_a + 4;
    float* ob = out + (size_t)bz*OUTC*HW + (size_t)(ph*16)*HW + gx;
    #pragma unroll
    for (int q = 0; q < 8; ++q) {
        float2 va = unpack2(accA[q]);
        float2 vb = unpack2(accB[q]);
        ob[(2*q  )*HW + gy_a*WWIDTH] = va.x;
        ob[(2*q+1)*HW + gy_a*WWIDTH] = va.y;
        ob[(2*q  )*HW + gy_b*WWIDTH] = vb.x;
        ob[(2*q+1)*HW + gy_b*WWIDTH] = vb.y;
    }
}

extern "C" void kernel_launch(void* const* d_in, const int* in_sizes, int n_in,
                              void* d_out, int out_size)
{
    const float* x  = (const float*)d_in[0];
    const float* cw = (const float*)d_in[1];
    const float* cb = (const float*)d_in[2];
    float* out = (float*)d_out;

    cudaFuncSetAttribute(pkc2d_kernel,
                         cudaFuncAttributeMaxDynamicSharedMemorySize, SMEM_BYTES);

    dim3 block(TW, TH, 1);
    dim3 grid(WWIDTH/TW, HH/TH, B_);
    pkc2d_kernel<<<grid, block, SMEM_BYTES>>>(x, cw, cb, out);
}

// round 17
// speedup vs baseline: 1.2388x; 1.1316x over previous
#include <cuda_runtime.h>
#include <math.h>

// x (2,16,256,256) f32, conv_w (32,16,4,4), conv_b (32) -> out (2,32,256,256) f32.
// Ring of 40 offsets (radius 5), stable-select 16 smallest sigmoid-sims,
// rank-indexed 32x(16*16) mat-vec per pixel.
// R16 structure (float4 halo, LDS.128 gathers, __expf + rcp.approx sigmoid,
// FFMA dot, d=xc-xr mat-vec) with sorted-insertion-buffer selection:
// keys = ((simbits-0x3C000000)<<6)|j  (u32, monotone in (sim, index)),
// 16-deep min/max insertion network replaces pairwise ranking.

#define B_      2
#define CCH     16
#define NC4     (CCH/4)        // 4 float4 channel-groups
#define HH      256
#define WWIDTH  256
#define HW      (HH*WWIDTH)
#define OUTC    32
#define NOFF    40
#define NSEL    16

#define TW 32
#define TH 8
#define NTHR (TW*TH)           // 256
#define SW 42                  // TW + 2*5
#define SH 18                  // TH + 2*5
#define CPLANE (SW*SH)         // 756
#define XS_FLOATS (CPLANE*CCH)        // 12096
#define WS_FLOATS (NSEL*CCH*OUTC)     // 8192
#define CB_FLOATS 32
// smem: xs + ws + cbs + selp(u16 [rank][tid]) + offtab(u16[64])
#define SMEM_BYTES ((XS_FLOATS + WS_FLOATS + CB_FLOATS)*4 + NSEL*NTHR*2 + 128)

// Ring offsets, order matching _prf_offsets:
//  j 0..10 : dx=-5,   dy=j-5
//  j 11..19: dx=j-15, dy=+5
//  j 20..30: dx=+5,   dy=j-25
//  j 31..39: dx=j-35, dy=-5
__host__ __device__ constexpr int dxOf(int j){ return j<11 ? -5 : (j<20 ? j-15 : (j<31 ? 5 : j-35)); }
__host__ __device__ constexpr int dyOf(int j){ return j<11 ? j-5 : (j<20 ? 5 : (j<31 ? j-25 : -5)); }
__host__ __device__ constexpr int offOf(int j){ return dxOf(j)*SW + dyOf(j); }

typedef unsigned long long u64;
typedef unsigned int u32;

#define KEY_BIAS 0x3C000000u   // sim >= 0.0078 guaranteed (19-sigma dot needed to break)

__device__ __forceinline__ u64 pack2(float a, float b){
    u64 r;
    asm("mov.b64 %0, {%1,%2};" : "=l"(r) : "f"(a), "f"(b));
    return r;
}
__device__ __forceinline__ void fma2(u64 &acc, u64 a, u64 b){
    asm("fma.rn.f32x2 %0, %1, %2, %0;" : "+l"(acc) : "l"(a), "l"(b));
}
__device__ __forceinline__ float2 unpack2(u64 v){
    float2 f;
    asm("mov.b64 {%0,%1}, %2;" : "=f"(f.x), "=f"(f.y) : "l"(v));
    return f;
}
__device__ __forceinline__ float rcp_approx(float v){
    float r;
    asm("rcp.approx.f32 %0, %1;" : "=f"(r) : "f"(v));
    return r;
}

__global__ __launch_bounds__(NTHR, 2)
void pkc2d_kernel(const float* __restrict__ x,
                  const float* __restrict__ cw,
                  const float* __restrict__ cb,
                  float* __restrict__ out)
{
    extern __shared__ float sm[];
    float4*         xs4    = reinterpret_cast<float4*>(sm);       // [c4][plane]
    float*          ws     = sm + XS_FLOATS;                      // [r][c][o]
    float*          cbs    = ws + WS_FLOATS;                      // [32]
    unsigned short* selp   = (unsigned short*)(cbs + CB_FLOATS);  // [rank][tid]
    unsigned short* offtab = selp + NSEL*NTHR;                    // [64] (40 used)

    const int tx = threadIdx.x, ty = threadIdx.y;
    const int tid = ty*TW + tx;
    const int gx0 = blockIdx.x*TW, gy0 = blockIdx.y*TH;
    const int bz  = blockIdx.z;

    const float* xb = x + (size_t)bz * CCH * HW;

    // ---- cooperative halo load: 4-channel float4 groups ----
    for (int i = tid; i < CPLANE*NC4; i += NTHR) {
        int c4   = i / CPLANE;
        int cell = i - c4*CPLANE;
        int sy   = cell / SW;
        int sx   = cell - sy*SW;
        int gy   = gy0 + sy - 5;
        int gxp  = gx0 + sx - 5;
        float4 v = make_float4(0.f, 0.f, 0.f, 0.f);
        if ((unsigned)gy < (unsigned)HH && (unsigned)gxp < (unsigned)WWIDTH) {
            const float* p = xb + (4*c4)*HW + gy*WWIDTH + gxp;
            v.x = p[0];
            v.y = p[HW];
            v.z = p[2*HW];
            v.w = p[3*HW];
        }
        xs4[i] = v;
    }
    // ws[((r*16)+c)*32 + o] = cw[o*256 + c*16 + r]
    for (int i = tid; i < WS_FLOATS; i += NTHR) {
        int o  = i & 31;
        int rc = i >> 5;
        int r  = rc >> 4;
        int c  = rc & 15;
        ws[i] = cw[o*256 + c*16 + r];
    }
    if (tid < 32) cbs[tid] = cb[tid];
    if (tid < NOFF) offtab[tid] = (unsigned short)(offOf(tid) + 512);
    __syncthreads();

    // ================= Phase 1: selection via sorted insertion buffer ========
    {
        const int base = (ty+5)*SW + (tx+5);

        float4 xc[NC4];
        #pragma unroll
        for (int c4 = 0; c4 < NC4; ++c4) xc[c4] = xs4[c4*CPLANE + base];

        // buf holds the 16 smallest keys seen, sorted ascending.
        u32 buf[NSEL];
        #pragma unroll
        for (int k = 0; k < NSEL; ++k) buf[k] = 0xFFFFFFFFu;

        // sims: FFMA-contracted sequential channel-order dot, then sigmoid
        // (REQUIRED per R5; ulp-robustness verified R13/R14/R16).
        // key = ((bits-BIAS)<<6)|j : strictly monotone in (sim, index), so
        // sorting keys == stable argsort of sims. Clamp guards 19-sigma tails.
        #pragma unroll
        for (int j = 0; j < NOFF; ++j) {
            const int off = offOf(j);
            float s = 0.f;
            #pragma unroll
            for (int c4 = 0; c4 < NC4; ++c4) {
                const float4 v = xs4[c4*CPLANE + base + off];
                s = __fmaf_rn(v.x, xc[c4].x, s);
                s = __fmaf_rn(v.y, xc[c4].y, s);
                s = __fmaf_rn(v.z, xc[c4].z, s);
                s = __fmaf_rn(v.w, xc[c4].w, s);
            }
            const float sim = rcp_approx(1.0f + __expf(s * -0.0625f));
            u32 bits = __float_as_uint(sim);
            bits = umax(bits, KEY_BIAS);
            u32 key = ((bits - KEY_BIAS) << 6) | (u32)j;
            #pragma unroll
            for (int k = 0; k < NSEL; ++k) {
                const u32 lo = umin(buf[k], key);
                key = umax(buf[k], key);
                buf[k] = lo;
            }
        }

        // buf[r] = r-th smallest key; low 6 bits = ring index j
        #pragma unroll
        for (int r = 0; r < NSEL; ++r)
            selp[r*NTHR + tid] = offtab[buf[r] & 63u];
    }
    __syncthreads();

    // ================= Phase 2: pixel-pair / half-OUTC mat-vec =================
    // thread t: ph = t>>7 -> o in [16*ph, 16*ph+16); pixels p0 = t&127 (rows 0..3)
    // and p1 = p0+128 (rows 4..7) of the 32x8 tile.
    const int pp = tid & 127;
    const int ph = tid >> 7;
    const int px = pp & 31;
    const int py = pp >> 5;

    const int b0 = (py+5)*SW + (px+5);
    const int b1 = b0 + 4*SW;

    float4 xc0[NC4], xc1[NC4];
    #pragma unroll
    for (int c4 = 0; c4 < NC4; ++c4) {
        xc0[c4] = xs4[c4*CPLANE + b0];
        xc1[c4] = xs4[c4*CPLANE + b1];
    }

    u64 accA[8], accB[8];
    #pragma unroll
    for (int q = 0; q < 8; ++q) {
        u64 seed = pack2(cbs[ph*16 + 2*q], cbs[ph*16 + 2*q + 1]);
        accA[q] = seed;
        accB[q] = seed;
    }

    #pragma unroll 1
    for (int r = 0; r < NSEL; ++r) {
        const int a0 = b0 + (int)selp[r*NTHR + pp]       - 512;
        const int a1 = b1 + (int)selp[r*NTHR + pp + 128] - 512;
        const ulonglong2* wq =
            reinterpret_cast<const ulonglong2*>(ws + (r << 9) + (ph << 4));
        #pragma unroll
        for (int c4 = 0; c4 < NC4; ++c4) {
            const float4 v0 = xs4[c4*CPLANE + a0];
            const float4 v1 = xs4[c4*CPLANE + a1];
            u64 dA, dB;
            #define CH_BLOCK(comp, choff)                                        \
            {                                                                    \
                dA = pack2(xc0[c4].comp - v0.comp, xc0[c4].comp - v0.comp);      \
                dB = pack2(xc1[c4].comp - v1.comp, xc1[c4].comp - v1.comp);      \
                const ulonglong2* wc_ = wq + (4*c4 + (choff))*8;                 \
                ulonglong2 w0 = wc_[0], w1 = wc_[1], w2 = wc_[2], w3 = wc_[3];   \
                fma2(accA[0], w0.x, dA); fma2(accB[0], w0.x, dB);                \
                fma2(accA[1], w0.y, dA); fma2(accB[1], w0.y, dB);                \
                fma2(accA[2], w1.x, dA); fma2(accB[2], w1.x, dB);                \
                fma2(accA[3], w1.y, dA); fma2(accB[3], w1.y, dB);                \
                fma2(accA[4], w2.x, dA); fma2(accB[4], w2.x, dB);                \
                fma2(accA[5], w2.y, dA); fma2(accB[5], w2.y, dB);                \
                fma2(accA[6], w3.x, dA); fma2(accB[6], w3.x, dB);                \
                fma2(accA[7], w3.y, dA); fma2(accB[7], w3.y, dB);                \
            }
            CH_BLOCK(x, 0)
            CH_BLOCK(y, 1)
            CH_BLOCK(z, 2)
            CH_BLOCK(w, 3)
            #undef CH_BLOCK
        }
    }

    // ---- store: 16 o-channels x 2 pixels ----
    const int gx = gx0 + px;
    const int gy_a = gy0 + py;
    const int gy_b = gy_a + 4;
    float* ob = out + (size_t)bz*OUTC*HW + (size_t)(ph*16)*HW + gx;
    #pragma unroll
    for (int q = 0; q < 8; ++q) {
        float2 va = unpack2(accA[q]);
        float2 vb = unpack2(accB[q]);
        ob[(2*q  )*HW + gy_a*WWIDTH] = va.x;
        ob[(2*q+1)*HW + gy_a*WWIDTH] = va.y;
        ob[(2*q  )*HW + gy_b*WWIDTH] = vb.x;
        ob[(2*q+1)*HW + gy_b*WWIDTH] = vb.y;
    }
}

extern "C" void kernel_launch(void* const* d_in, const int* in_sizes, int n_in,
                              void* d_out, int out_size)
{
    const float* x  = (const float*)d_in[0];
    const float* cw = (const float*)d_in[1];
    const float* cb = (const float*)d_in[2];
    float* out = (float*)d_out;

    cudaFuncSetAttribute(pkc2d_kernel,
                         cudaFuncAttributeMaxDynamicSharedMemorySize, SMEM_BYTES);

    dim3 block(TW, TH, 1);
    dim3 grid(WWIDTH/TW, HH/TH, B_);
    pkc2d_kernel<<<grid, block, SMEM_BYTES>>>(x, cw, cb, out);
}